// round 4
// baseline (speedup 1.0000x reference)
#include <cuda_runtime.h>

// max_general_2x2: the reference relu chain collapses exactly to a
// 2x2 stride-2 max-pool, fp32:
//   u1+u2-u3 = relu(a-b)+b = max(a,b);  s = max(c,d)
//   out = relu(max(a,b)-s)+s = max(max(a,b), max(c,d))
//
// Input  x: (32, 64, 112, 112) fp32   -> 25,690,112 elems (102.8 MB)
// Output  : (32, 64, 56, 56)   fp32   ->  6,422,528 elems ( 25.7 MB)
// Pure HBM-bound; target ~19 us.

#define NC_PLANES   (32 * 64)      // 2048 planes
#define IN_W        112
#define IN_PLANE    (112 * 112)    // 12544
#define OUT_W       56
#define V4_PER_ROW  (OUT_W / 4)    // 14 float4 per output row
#define TOTAL_V4    (NC_PLANES * OUT_W * V4_PER_ROW)  // 1,605,632

__global__ __launch_bounds__(256) void maxpool2x2_kernel(
    const float* __restrict__ in, float4* __restrict__ out, int total)
{
    int idx = blockIdx.x * blockDim.x + threadIdx.x;
    if (idx >= total) return;

    // idx -> (plane, oh, j) where j indexes a float4 (4 output cols)
    int j     = idx % V4_PER_ROW;           // 0..13
    int t     = idx / V4_PER_ROW;
    int oh    = t % OUT_W;                  // 0..55
    int plane = t / OUT_W;                  // 0..2047

    // Input rows 2*oh, 2*oh+1; cols 8*j .. 8*j+7. All 16B aligned.
    const float4* ip0 = reinterpret_cast<const float4*>(
        in + (size_t)plane * IN_PLANE + (2 * oh) * IN_W + 8 * j);
    const float4* ip1 = reinterpret_cast<const float4*>(
        reinterpret_cast<const float*>(ip0) + IN_W);

    // 4 independent LDG.128, front-batched (MLP=4)
    float4 a0 = ip0[0];
    float4 a1 = ip0[1];
    float4 b0 = ip1[0];
    float4 b1 = ip1[1];

    float4 o;
    o.x = fmaxf(fmaxf(a0.x, a0.y), fmaxf(b0.x, b0.y));
    o.y = fmaxf(fmaxf(a0.z, a0.w), fmaxf(b0.z, b0.w));
    o.z = fmaxf(fmaxf(a1.x, a1.y), fmaxf(b1.x, b1.y));
    o.w = fmaxf(fmaxf(a1.z, a1.w), fmaxf(b1.z, b1.w));

    out[idx] = o;
}

extern "C" void kernel_launch(void* const* d_in, const int* in_sizes, int n_in,
                              void* d_out, int out_size)
{
    const float* x = (const float*)d_in[0];
    float4* out = (float4*)d_out;

    const int total = TOTAL_V4;             // 1,605,632 float4 outputs
    const int threads = 256;
    const int blocks = (total + threads - 1) / threads;  // 6272
    maxpool2x2_kernel<<<blocks, threads>>>(x, out, total);
}